// round 6
// baseline (speedup 1.0000x reference)
#include <cuda_runtime.h>
#include <cstdint>

#define BB 32
#define CC 64
#define TT_FULL 16384
#define KW 21
#define TCV (TT_FULL - KW + 1)   /* 16364 */
#define TTILE 64
#define NTILES ((TCV + TTILE - 1) / TTILE)  /* 256 */

typedef unsigned long long ull;

// ---------------- device scratch (no allocations allowed) ----------------
__device__ float g_y1[BB * CC * TT_FULL];          // raw conv1 output (padded T stride)
__device__ float g_y2[BB * CC * TT_FULL];          // raw conv2 output
__device__ ull   g_wtp[2][CC * CC * KW];           // weights transposed [i][o][k], packed {w,w}
__device__ double g_sum[2][CC];
__device__ double g_sq[2][CC];
__device__ float g_feat[BB * 384];

__device__ __forceinline__ void ffma2(ull& acc, ull a, ull w) {
    asm("fma.rn.f32x2 %0, %1, %2, %0;" : "+l"(acc) : "l"(a), "l"(w));
}
__device__ __forceinline__ float f2lo(ull v) { return __uint_as_float((unsigned)v); }
__device__ __forceinline__ float f2hi(ull v) { return __uint_as_float((unsigned)(v >> 32)); }

// ---------------- prep kernels ----------------
__global__ void zero_stats_k() {
    int t = threadIdx.x;
    if (t < 128) { ((double*)g_sum)[t] = 0.0; ((double*)g_sq)[t] = 0.0; }
}

__global__ void pack_weights_k(const float* __restrict__ w1, const float* __restrict__ w2) {
    int gid = blockIdx.x * blockDim.x + threadIdx.x;
    const int per = CC * CC * KW;  // 86016
    if (gid >= 2 * per) return;
    int conv = gid / per;
    int r = gid % per;
    int i = r / (CC * KW);
    int q = r % (CC * KW);
    int o = q / KW;
    int k = q % KW;
    const float* w = conv ? w2 : w1;
    unsigned u = __float_as_uint(w[(o * CC + i) * KW + k]);
    g_wtp[conv][r] = ((ull)u << 32) | (ull)u;
}

// ---------------- conv kernel (even/odd polyphase, fma.rn.f32x2) ----------------
// block: 256 threads. o = tid>>2 (64 out channels), tg = tid&3 (4 groups of 16 t).
// Each thread: 16 output positions, one output channel, one conv.
__global__ void __launch_bounds__(256) conv_k(const float* __restrict__ x) {
    __shared__ __align__(16) float xs[CC][84];     // 64 x (TTILE + 20) = 21.5 KB
    __shared__ ull ws[2][CC * KW];                 // double-buffered weight slice, 21 KB
    __shared__ float s_sum[CC];
    __shared__ float s_sq[CC];

    const int tid  = threadIdx.x;
    const int tile = blockIdx.x;
    const int b    = blockIdx.y;
    const int conv = blockIdx.z;
    const int t0   = tile * TTILE;

    // stage x tile (coalesced)
    for (int idx = tid; idx < CC * 84; idx += 256) {
        int i = idx / 84, j = idx % 84;
        int t = t0 + j;
        xs[i][j] = (t < TT_FULL) ? x[(b * CC + i) * TT_FULL + t] : 0.f;
    }
    const ull* wt = g_wtp[conv];
    for (int idx = tid; idx < CC * KW; idx += 256) ws[0][idx] = wt[idx];
    __syncthreads();

    const int o = tid >> 2;
    const int tg = tid & 3;
    const int base = tg * 16;

    ull accE[8], accO[9];
#pragma unroll
    for (int p = 0; p < 8; p++) accE[p] = 0ULL;
#pragma unroll
    for (int j = 0; j < 9; j++) accO[j] = 0ULL;

    int buf = 0;
#pragma unroll 1
    for (int i = 0; i < CC; i++) {
        // prefetch next weight slice into registers (hides L2 latency behind FMAs)
        ull pre[6];
        const bool do_pre = (i + 1 < CC);
        if (do_pre) {
            const ull* src = wt + (i + 1) * (CC * KW);
#pragma unroll
            for (int u = 0; u < 6; u++) {
                int idx = tid + u * 256;
                if (idx < CC * KW) pre[u] = src[idx];
            }
        }

        // load 36 x values = 18 aligned pairs via 9x LDS.128
        ull Xe[18];
        const ulonglong2* xp = reinterpret_cast<const ulonglong2*>(&xs[i][base]);
#pragma unroll
        for (int m = 0; m < 9; m++) { ulonglong2 v = xp[m]; Xe[2 * m] = v.x; Xe[2 * m + 1] = v.y; }

        const ull* w = &ws[buf][o * KW];
        // even taps: accE[p] = {y[2p], y[2p+1]}
#pragma unroll
        for (int kk = 0; kk <= 10; kk++) {
            ull wk = w[2 * kk];
#pragma unroll
            for (int p = 0; p < 8; p++) ffma2(accE[p], Xe[p + kk], wk);
        }
        // odd taps: accO[j] = {y[2j-1], y[2j]}
#pragma unroll
        for (int kk = 0; kk <= 9; kk++) {
            ull wk = w[2 * kk + 1];
#pragma unroll
            for (int j = 0; j < 9; j++) ffma2(accO[j], Xe[j + kk], wk);
        }

        if (do_pre) {
#pragma unroll
            for (int u = 0; u < 6; u++) {
                int idx = tid + u * 256;
                if (idx < CC * KW) ws[buf ^ 1][idx] = pre[u];
            }
        }
        __syncthreads();
        buf ^= 1;
    }

    // combine polyphase accumulators
    float yv[16];
#pragma unroll
    for (int p = 0; p < 8; p++) {
        yv[2 * p]     = f2lo(accE[p]) + f2hi(accO[p]);
        yv[2 * p + 1] = f2hi(accE[p]) + f2lo(accO[p + 1]);
    }

    float* yout = (conv ? g_y2 : g_y1) + (size_t)(b * CC + o) * TT_FULL + t0 + base;
    float lsum = 0.f, lsq = 0.f;
    const int tstart = t0 + base;
    if (tstart + 16 <= TCV) {
#pragma unroll
        for (int q = 0; q < 4; q++) {
            float4 v = make_float4(yv[4 * q], yv[4 * q + 1], yv[4 * q + 2], yv[4 * q + 3]);
            reinterpret_cast<float4*>(yout)[q] = v;
        }
#pragma unroll
        for (int q = 0; q < 16; q++) { lsum += yv[q]; lsq += yv[q] * yv[q]; }
    } else {
#pragma unroll
        for (int q = 0; q < 16; q++) {
            if (tstart + q < TCV) { yout[q] = yv[q]; lsum += yv[q]; lsq += yv[q] * yv[q]; }
        }
    }

    // per-channel partial stats -> shared -> global double atomics
    if (tid < CC) { s_sum[tid] = 0.f; s_sq[tid] = 0.f; }
    __syncthreads();
    atomicAdd(&s_sum[o], lsum);
    atomicAdd(&s_sq[o], lsq);
    __syncthreads();
    if (tid < CC) {
        atomicAdd(&g_sum[conv][tid], (double)s_sum[tid]);
        atomicAdd(&g_sq[conv][tid], (double)s_sq[tid]);
    }
}

// ---------------- pooling kernel: BN + LeakyReLU + SPP windows ----------------
__global__ void __launch_bounds__(256) pool_k(const int* __restrict__ orig_len,
                                              const float* __restrict__ g1, const float* __restrict__ b1,
                                              const float* __restrict__ g2, const float* __restrict__ b2) {
    const int c = blockIdx.x, b = blockIdx.y;
    const int tid = threadIdx.x;
    const int L = orig_len[b] - (KW - 1);
    const int strd = L >> 1;         // floor(L/2)
    const int kern = L - strd;       // ceil(L/2)

    const double CNT = (double)BB * (double)TCV;
    double m1 = g_sum[0][c] / CNT;
    double v1 = g_sq[0][c] / CNT - m1 * m1;
    double m2 = g_sum[1][c] / CNT;
    double v2 = g_sq[1][c] / CNT - m2 * m2;
    const float sc1 = (float)((double)g1[c] / sqrt(v1 + 1e-5));
    const float sh1 = (float)((double)b1[c] - m1 * ((double)g1[c] / sqrt(v1 + 1e-5)));
    const float sc2 = (float)((double)g2[c] / sqrt(v2 + 1e-5));
    const float sh2 = (float)((double)b2[c] - m2 * ((double)g2[c] / sqrt(v2 + 1e-5)));

    const float* y1r = g_y1 + (size_t)(b * CC + c) * TT_FULL;
    const float* y2r = g_y2 + (size_t)(b * CC + c) * TT_FULL;

    const float NEG = -3.402823466e38f;
    float mx0 = NEG, mx1 = NEG, mx2 = NEG;
    float s0 = 0.f, s1 = 0.f, s2 = 0.f;
    for (int t = tid; t < L; t += 256) {
        float z1 = sc1 * y1r[t] + sh1; z1 = (z1 > 0.f) ? z1 : 0.01f * z1;
        mx0 = fmaxf(mx0, z1);
        if (t < kern) mx1 = fmaxf(mx1, z1);
        if (t >= strd) mx2 = fmaxf(mx2, z1);
        float z2 = sc2 * y2r[t] + sh2; z2 = (z2 > 0.f) ? z2 : 0.01f * z2;
        s0 += z2;
        if (t < kern) s1 += z2;
        if (t >= strd) s2 += z2;
    }
    // warp reduce
#pragma unroll
    for (int off = 16; off; off >>= 1) {
        mx0 = fmaxf(mx0, __shfl_down_sync(0xffffffffu, mx0, off));
        mx1 = fmaxf(mx1, __shfl_down_sync(0xffffffffu, mx1, off));
        mx2 = fmaxf(mx2, __shfl_down_sync(0xffffffffu, mx2, off));
        s0 += __shfl_down_sync(0xffffffffu, s0, off);
        s1 += __shfl_down_sync(0xffffffffu, s1, off);
        s2 += __shfl_down_sync(0xffffffffu, s2, off);
    }
    __shared__ float red[8][6];
    if ((tid & 31) == 0) {
        int w = tid >> 5;
        red[w][0] = mx0; red[w][1] = mx1; red[w][2] = mx2;
        red[w][3] = s0;  red[w][4] = s1;  red[w][5] = s2;
    }
    __syncthreads();
    if (tid == 0) {
        float a0 = red[0][0], a1 = red[0][1], a2 = red[0][2];
        float t0 = red[0][3], t1 = red[0][4], t2 = red[0][5];
#pragma unroll
        for (int w = 1; w < 8; w++) {
            a0 = fmaxf(a0, red[w][0]); a1 = fmaxf(a1, red[w][1]); a2 = fmaxf(a2, red[w][2]);
            t0 += red[w][3]; t1 += red[w][4]; t2 += red[w][5];
        }
        float* f = g_feat + b * 384;
        // p1 (max branch): level0 [c], level1 [64 + 2c + j]
        f[c] = a0;
        f[64 + 2 * c]     = a1;
        f[64 + 2 * c + 1] = a2;
        // p2 (avg branch): offset 192
        f[192 + c] = t0 / (float)L;
        f[192 + 64 + 2 * c]     = t1 / (float)kern;
        f[192 + 64 + 2 * c + 1] = t2 / (float)kern;
    }
}

// ---------------- FC head ----------------
__global__ void fc_k(const float* __restrict__ fc_w, const float* __restrict__ fc_b,
                     float* __restrict__ out) {
    int tid = threadIdx.x;
    if (tid >= BB * 2) return;
    int b = tid >> 1, task = tid & 1;
    const float* f = g_feat + b * 384;
    const float* w = fc_w + task * 384;
    float acc = fc_b[task];
#pragma unroll 8
    for (int j = 0; j < 384; j++) acc += f[j] * w[j];
    out[b * 2 + task] = acc;
}

// ---------------- launch ----------------
extern "C" void kernel_launch(void* const* d_in, const int* in_sizes, int n_in,
                              void* d_out, int out_size) {
    const float* x        = (const float*)d_in[0];
    const int*   orig_len = (const int*)d_in[1];
    const float* w1   = (const float*)d_in[2];
    const float* g1   = (const float*)d_in[3];
    const float* b1   = (const float*)d_in[4];
    const float* w2   = (const float*)d_in[5];
    const float* g2   = (const float*)d_in[6];
    const float* b2   = (const float*)d_in[7];
    const float* fc_w = (const float*)d_in[8];
    const float* fc_b = (const float*)d_in[9];
    float* out = (float*)d_out;

    zero_stats_k<<<1, 128>>>();
    pack_weights_k<<<(2 * CC * CC * KW + 255) / 256, 256>>>(w1, w2);

    dim3 cgrid(NTILES, BB, 2);
    conv_k<<<cgrid, 256>>>(x);

    dim3 pgrid(CC, BB);
    pool_k<<<pgrid, 256>>>(orig_len, g1, b1, g2, b2);

    fc_k<<<1, 64>>>(fc_w, fc_b, out);
}

// round 9
// speedup vs baseline: 3.2864x; 3.2864x over previous
#include <cuda_runtime.h>
#include <cuda_bf16.h>
#include <cstdint>
#include <cfloat>

#define BB 32
#define TT 16384
#define TP 16416
#define KW 21
#define TCV (TT - KW + 1)   /* 16364 */

// smem layout (dynamic): A-hi[148x128B] | A-lo | B[2 bufs][hi 16K + lo 16K]
#define OFF_AH 0
#define OFF_AL 18944
#define OFF_B  37888
#define SMEM_TOTAL 103424

// ---------------- device scratch ----------------
__device__ __align__(16) __nv_bfloat16 g_xh[BB * TP * 64];
__device__ __align__(16) __nv_bfloat16 g_xl[BB * TP * 64];
__device__ __align__(16) __nv_bfloat16 g_wbh[KW * 128 * 64];
__device__ __align__(16) __nv_bfloat16 g_wbl[KW * 128 * 64];
__device__ __align__(16) float g_y2[(size_t)BB * 64 * TT];   /* conv2 raw [b][c][t] */
__device__ float g_bs[256 * 4096];                           /* stats partials [slot][cta] */
__device__ float g_part[32 * 64 * 3 * 128];                  /* max partials [b][c][w][tile] */
__device__ double g_sumd[128];
__device__ double g_sqd[128];
__device__ float g_feat[BB * 384];

// ---------------- asm helpers (all sm_80-portable) ----------------
__device__ __forceinline__ uint32_t smem_u32(const void* p) {
    uint32_t r;
    asm("{ .reg .u64 t; cvta.to.shared.u64 t, %1; cvt.u32.u64 %0, t; }" : "=r"(r) : "l"(p));
    return r;
}
__device__ __forceinline__ void cp16(uint32_t d, const void* s) {
    asm volatile("cp.async.cg.shared.global [%0], [%1], 16;" :: "r"(d), "l"(s));
}
#define CP_COMMIT asm volatile("cp.async.commit_group;" ::: "memory")
#define CP_WAIT1  asm volatile("cp.async.wait_group 1;" ::: "memory")
#define CP_WAIT0  asm volatile("cp.async.wait_group 0;" ::: "memory")

__device__ __forceinline__ void ldsm4(uint32_t* r, uint32_t a) {
    asm volatile("ldmatrix.sync.aligned.m8n8.x4.shared.b16 {%0,%1,%2,%3}, [%4];"
        : "=r"(r[0]), "=r"(r[1]), "=r"(r[2]), "=r"(r[3]) : "r"(a));
}
#define MMA16816(D, A, B) asm volatile( \
    "mma.sync.aligned.m16n8k16.row.col.f32.bf16.bf16.f32 " \
    "{%0,%1,%2,%3}, {%4,%5,%6,%7}, {%8,%9}, {%0,%1,%2,%3};" \
    : "+f"((D)[0]), "+f"((D)[1]), "+f"((D)[2]), "+f"((D)[3]) \
    : "r"((A)[0]), "r"((A)[1]), "r"((A)[2]), "r"((A)[3]), "r"((B)[0]), "r"((B)[1]))

__device__ __forceinline__ uint32_t swz(uint32_t base, int row, int col) {
    uint32_t off = (uint32_t)(row * 128 + col);
    return base + (off ^ ((off >> 3) & 0x70));
}

// ---------------- prep kernels ----------------
__global__ void zero_pad_k() {
    int idx = blockIdx.x * blockDim.x + threadIdx.x;
    if (idx >= 65536) return;
    int b = idx >> 11, row = TT + ((idx >> 6) & 31), c = idx & 63;
    size_t off = ((size_t)b * TP + row) * 64 + c;
    g_xh[off] = __float2bfloat16(0.f);
    g_xl[off] = __float2bfloat16(0.f);
}

__global__ void __launch_bounds__(256) prep_x_k(const float* __restrict__ x) {
    __shared__ float xs[64][65];
    int b = blockIdx.y, t0 = blockIdx.x * 64, tid = threadIdx.x;
    for (int idx = tid; idx < 4096; idx += 256) {
        int c = idx >> 6, t = idx & 63;
        xs[c][t] = x[((size_t)b * 64 + c) * TT + t0 + t];
    }
    __syncthreads();
    for (int idx = tid; idx < 4096; idx += 256) {
        int t = idx >> 6, c = idx & 63;
        float v = xs[c][t];
        __nv_bfloat16 h = __float2bfloat16(v);
        __nv_bfloat16 l = __float2bfloat16(v - __bfloat162float(h));
        size_t off = ((size_t)b * TP + t0 + t) * 64 + c;
        g_xh[off] = h;
        g_xl[off] = l;
    }
}

__global__ void prep_w_k(const float* __restrict__ w1, const float* __restrict__ w2) {
    int gid = blockIdx.x * blockDim.x + threadIdx.x;
    if (gid >= KW * 128 * 64) return;
    int k = gid >> 13, o = (gid >> 6) & 127, i = gid & 63;
    const float* w = (o >= 64) ? w2 : w1;
    float v = w[((o & 63) * 64 + i) * KW + k];
    __nv_bfloat16 h = __float2bfloat16(v);
    __nv_bfloat16 l = __float2bfloat16(v - __bfloat162float(h));
    g_wbh[gid] = h;
    g_wbl[gid] = l;
}

// ---------------- conv via mma.sync (HMMA bf16, hi/lo 3-pass) ----------------
__global__ void __launch_bounds__(256) conv_k(const int* __restrict__ orig_len) {
    extern __shared__ __align__(16) char sm[];
    const int tid = threadIdx.x, wid = tid >> 5, lane = tid & 31;
    const int tb = blockIdx.x, b = blockIdx.y;
    const int t0 = tb * 128;
    const uint32_t smb = smem_u32(sm);
    const int wm = wid >> 1;      /* t-group 0..3 (32 rows)  */
    const int wn = wid & 1;       /* o-half 0..1 (64 cols)   */

    // ---- prologue: async-stage A window (148 rows) + B tap 0 ----
    {
        const uint4* sH = (const uint4*)g_xh + ((size_t)b * TP + t0) * 8;
        const uint4* sL = (const uint4*)g_xl + ((size_t)b * TP + t0) * 8;
        for (int idx = tid; idx < 1184; idx += 256) {
            uint32_t off = (uint32_t)((idx >> 3) * 128 + (idx & 7) * 16);
            uint32_t d = off ^ ((off >> 3) & 0x70);
            cp16(smb + OFF_AH + d, sH + idx);
            cp16(smb + OFF_AL + d, sL + idx);
        }
        const uint4* wH = (const uint4*)g_wbh;
        const uint4* wL = (const uint4*)g_wbl;
        for (int idx = tid; idx < 1024; idx += 256) {
            uint32_t off = (uint32_t)((idx >> 3) * 128 + (idx & 7) * 16);
            uint32_t d = off ^ ((off >> 3) & 0x70);
            cp16(smb + OFF_B + d, wH + idx);
            cp16(smb + OFF_B + 16384 + d, wL + idx);
        }
        CP_COMMIT;
    }

    float acc[2][8][4];
#pragma unroll
    for (int mt = 0; mt < 2; mt++)
#pragma unroll
        for (int nt = 0; nt < 8; nt++)
#pragma unroll
            for (int e = 0; e < 4; e++) acc[mt][nt][e] = 0.f;

#pragma unroll 1
    for (int k = 0; k < 21; k++) {
        const int buf = k & 1;
        if (k < 20) {   // stage next tap into other buffer
            const uint4* wH = (const uint4*)g_wbh + (k + 1) * 1024;
            const uint4* wL = (const uint4*)g_wbl + (k + 1) * 1024;
            uint32_t db = smb + OFF_B + (buf ^ 1) * 32768;
            for (int idx = tid; idx < 1024; idx += 256) {
                uint32_t off = (uint32_t)((idx >> 3) * 128 + (idx & 7) * 16);
                uint32_t d = off ^ ((off >> 3) & 0x70);
                cp16(db + d, wH + idx);
                cp16(db + 16384 + d, wL + idx);
            }
            CP_COMMIT;
            CP_WAIT1;
        } else {
            CP_WAIT0;
        }
        __syncthreads();

        const uint32_t bBaseH = smb + OFF_B + buf * 32768;
        const uint32_t bBaseL = bBaseH + 16384;
#pragma unroll
        for (int ks = 0; ks < 4; ks++) {
            const int colA = ks * 32 + ((lane >> 4) << 4);
            uint32_t ah[2][4], al[2][4], bh[8][2], bl[8][2];
#pragma unroll
            for (int mt = 0; mt < 2; mt++) {
                int row = wm * 32 + k + mt * 16 + (lane & 15);
                ldsm4(ah[mt], swz(smb + OFF_AH, row, colA));
                ldsm4(al[mt], swz(smb + OFF_AL, row, colA));
            }
#pragma unroll
            for (int g = 0; g < 4; g++) {
                int row = wn * 64 + g * 16 + (lane & 15);
                uint32_t r[4];
                ldsm4(r, swz(bBaseH, row, colA));
                bh[2 * g][0] = r[0]; bh[2 * g][1] = r[2];
                bh[2 * g + 1][0] = r[1]; bh[2 * g + 1][1] = r[3];
                ldsm4(r, swz(bBaseL, row, colA));
                bl[2 * g][0] = r[0]; bl[2 * g][1] = r[2];
                bl[2 * g + 1][0] = r[1]; bl[2 * g + 1][1] = r[3];
            }
#pragma unroll
            for (int mt = 0; mt < 2; mt++)
#pragma unroll
                for (int nt = 0; nt < 8; nt++) MMA16816(acc[mt][nt], ah[mt], bh[nt]);
#pragma unroll
            for (int mt = 0; mt < 2; mt++)
#pragma unroll
                for (int nt = 0; nt < 8; nt++) MMA16816(acc[mt][nt], al[mt], bh[nt]);
#pragma unroll
            for (int mt = 0; mt < 2; mt++)
#pragma unroll
                for (int nt = 0; nt < 8; nt++) MMA16816(acc[mt][nt], ah[mt], bl[nt]);
        }
        __syncthreads();
    }

    // ---- epilogue: stage D[o][t] in smem (reuse A/B region) ----
    float* smD = (float*)sm;    // 128 x 132 floats
    {
        const int lo2 = 2 * (lane & 3), lt = lane >> 2;
#pragma unroll
        for (int mt = 0; mt < 2; mt++)
#pragma unroll
            for (int nt = 0; nt < 8; nt++) {
                int o = wn * 64 + nt * 8 + lo2;
                int t = wm * 32 + mt * 16 + lt;
                smD[o * 132 + t]           = acc[mt][nt][0];
                smD[(o + 1) * 132 + t]     = acc[mt][nt][1];
                smD[o * 132 + t + 8]       = acc[mt][nt][2];
                smD[(o + 1) * 132 + t + 8] = acc[mt][nt][3];
            }
    }
    __syncthreads();

    const int L = orig_len[b] - (KW - 1);
    const int strd = L >> 1, kern = L - strd;
    const int cta = b * 128 + tb;

#pragma unroll 1
    for (int oi = 0; oi < 16; oi++) {
        const int o = wid * 16 + oi;
        float4 v = *(const float4*)(smD + o * 132 + lane * 4);
        float vv[4] = {v.x, v.y, v.z, v.w};
        float s = 0.f, q = 0.f;
        float m0 = -FLT_MAX, m1 = -FLT_MAX, m2 = -FLT_MAX;
        const int tg0 = t0 + lane * 4;
#pragma unroll
        for (int e = 0; e < 4; e++) {
            int tg = tg0 + e;
            float xv = vv[e];
            if (tg < TCV) { s += xv; q += xv * xv; }
            if (o < 64) {
                if (tg < L) { m0 = fmaxf(m0, xv); if (tg >= strd) m2 = fmaxf(m2, xv); }
                if (tg < kern) m1 = fmaxf(m1, xv);
            }
        }
        if (o >= 64)   // conv2 raw output needed elementwise for avg-pool(leaky)
            *(float4*)(g_y2 + ((size_t)(b * 64 + (o - 64))) * TT + t0 + lane * 4) = v;
#pragma unroll
        for (int off = 16; off; off >>= 1) {
            s += __shfl_xor_sync(0xffffffffu, s, off);
            q += __shfl_xor_sync(0xffffffffu, q, off);
            m0 = fmaxf(m0, __shfl_xor_sync(0xffffffffu, m0, off));
            m1 = fmaxf(m1, __shfl_xor_sync(0xffffffffu, m1, off));
            m2 = fmaxf(m2, __shfl_xor_sync(0xffffffffu, m2, off));
        }
        if (lane == 0) {
            g_bs[o * 4096 + cta] = s;
            g_bs[(128 + o) * 4096 + cta] = q;
            if (o < 64) {
                float* p = g_part + ((b * 64 + o) * 3) * 128 + tb;
                p[0] = m0; p[128] = m1; p[256] = m2;
            }
        }
    }
}

// ---------------- BN stats reduce ----------------
__global__ void __launch_bounds__(256) stats_k() {
    __shared__ double sd[256];
    int slot = blockIdx.x, tid = threadIdx.x;
    double a = 0.0;
    for (int i = tid; i < 4096; i += 256) a += (double)g_bs[(size_t)slot * 4096 + i];
    sd[tid] = a;
    __syncthreads();
    for (int s = 128; s; s >>= 1) { if (tid < s) sd[tid] += sd[tid + s]; __syncthreads(); }
    if (tid == 0) {
        if (slot < 128) g_sumd[slot] = sd[0];
        else g_sqd[slot - 128] = sd[0];
    }
}

// ---------------- max-branch features (conv1): reduce tiles + BN + leaky ----------------
__global__ void featmax_k(const float* __restrict__ g1, const float* __restrict__ b1) {
    int b = blockIdx.x, j = threadIdx.x;   // 192 threads
    if (j >= 192) return;
    int o, w;
    if (j < 64) { o = j; w = 0; } else { o = (j - 64) >> 1; w = 1 + ((j - 64) & 1); }
    const float* p = g_part + ((b * 64 + o) * 3 + w) * 128;
    float m = -FLT_MAX;
    for (int t = 0; t < 128; t++) m = fmaxf(m, p[t]);
    const double CNT = (double)BB * (double)TCV;
    double mu = g_sumd[o] / CNT;
    double va = g_sqd[o] / CNT - mu * mu;
    double scd = (double)g1[o] / sqrt(va + 1e-5);
    float z = (float)(scd * (double)m + ((double)b1[o] - mu * scd));
    z = (z > 0.f) ? z : 0.01f * z;
    g_feat[b * 384 + j] = z;
}

// ---------------- avg-branch (conv2): BN + leaky + windowed sums ----------------
__global__ void __launch_bounds__(256) pool2_k(const int* __restrict__ orig_len,
                                               const float* __restrict__ g2, const float* __restrict__ b2) {
    const int c = blockIdx.x, b = blockIdx.y;
    const int tid = threadIdx.x;
    const int L = orig_len[b] - (KW - 1);
    const int strd = L >> 1, kern = L - strd;

    const double CNT = (double)BB * (double)TCV;
    double mu = g_sumd[64 + c] / CNT;
    double va = g_sqd[64 + c] / CNT - mu * mu;
    double scd = (double)g2[c] / sqrt(va + 1e-5);
    const float sc = (float)scd;
    const float sh = (float)((double)b2[c] - mu * scd);

    const float* yr = g_y2 + ((size_t)b * 64 + c) * TT;
    float s0 = 0.f, s1 = 0.f, s2 = 0.f;
    for (int t = tid; t < L; t += 256) {
        float z = sc * yr[t] + sh;
        z = (z > 0.f) ? z : 0.01f * z;
        s0 += z;
        if (t < kern) s1 += z;
        if (t >= strd) s2 += z;
    }
#pragma unroll
    for (int off = 16; off; off >>= 1) {
        s0 += __shfl_down_sync(0xffffffffu, s0, off);
        s1 += __shfl_down_sync(0xffffffffu, s1, off);
        s2 += __shfl_down_sync(0xffffffffu, s2, off);
    }
    __shared__ float red[8][3];
    if ((tid & 31) == 0) { int w = tid >> 5; red[w][0] = s0; red[w][1] = s1; red[w][2] = s2; }
    __syncthreads();
    if (tid == 0) {
        float t0v = 0.f, t1v = 0.f, t2v = 0.f;
#pragma unroll
        for (int w = 0; w < 8; w++) { t0v += red[w][0]; t1v += red[w][1]; t2v += red[w][2]; }
        float* f = g_feat + b * 384;
        f[192 + c] = t0v / (float)L;
        f[256 + 2 * c]     = t1v / (float)kern;
        f[256 + 2 * c + 1] = t2v / (float)kern;
    }
}

// ---------------- FC head ----------------
__global__ void fc_k(const float* __restrict__ fc_w, const float* __restrict__ fc_b,
                     float* __restrict__ out) {
    int tid = threadIdx.x;
    if (tid >= BB * 2) return;
    int b = tid >> 1, task = tid & 1;
    const float* f = g_feat + b * 384;
    const float* w = fc_w + task * 384;
    float acc = fc_b[task];
#pragma unroll 8
    for (int j = 0; j < 384; j++) acc += f[j] * w[j];
    out[b * 2 + task] = acc;
}

// ---------------- launch ----------------
extern "C" void kernel_launch(void* const* d_in, const int* in_sizes, int n_in,
                              void* d_out, int out_size) {
    const float* x        = (const float*)d_in[0];
    const int*   orig_len = (const int*)d_in[1];
    const float* w1   = (const float*)d_in[2];
    const float* g1   = (const float*)d_in[3];
    const float* b1   = (const float*)d_in[4];
    const float* w2   = (const float*)d_in[5];
    const float* g2   = (const float*)d_in[6];
    const float* b2   = (const float*)d_in[7];
    const float* fc_w = (const float*)d_in[8];
    const float* fc_b = (const float*)d_in[9];
    float* out = (float*)d_out;

    cudaFuncSetAttribute(conv_k, cudaFuncAttributeMaxDynamicSharedMemorySize, SMEM_TOTAL);

    zero_pad_k<<<256, 256>>>();
    dim3 xg(256, BB);
    prep_x_k<<<xg, 256>>>(x);
    prep_w_k<<<(KW * 128 * 64 + 255) / 256, 256>>>(w1, w2);

    dim3 cg(128, BB);
    conv_k<<<cg, 256, SMEM_TOTAL>>>(orig_len);

    stats_k<<<256, 256>>>();
    featmax_k<<<BB, 192>>>(g1, b1);
    dim3 pg(64, BB);
    pool2_k<<<pg, 256>>>(orig_len, g2, b2);

    fc_k<<<1, 64>>>(fc_w, fc_b, out);
}

// round 10
// speedup vs baseline: 4.5333x; 1.3794x over previous
#include <cuda_runtime.h>
#include <cuda_fp16.h>
#include <cstdint>
#include <cfloat>

#define BB 32
#define TT 16384
#define TP 16416
#define KW 21
#define TCV (TT - KW + 1)   /* 16364 */

// smem layout (dynamic): A-hi[148x128B] | A-lo | B[2 bufs][16K]
#define OFF_AH 0
#define OFF_AL 18944
#define OFF_B  37888
#define SMEM_TOTAL 70656

// ---------------- device scratch ----------------
__device__ __align__(16) __half g_xh[BB * TP * 64];
__device__ __align__(16) __half g_xl[BB * TP * 64];
__device__ __align__(16) __half g_wh[KW * 128 * 64];
__device__ __align__(16) float g_y2[(size_t)BB * 64 * TT];   /* conv2 raw [b][c][t] */
__device__ float g_bs[256 * 4096];                           /* stats partials [slot][cta] */
__device__ float g_part[32 * 64 * 3 * 128];                  /* max partials [b][c][w][tile] */
__device__ double g_sumd[128];
__device__ double g_sqd[128];
__device__ float g_feat[BB * 384];

// ---------------- asm helpers (sm_80-portable) ----------------
__device__ __forceinline__ uint32_t smem_u32(const void* p) {
    uint32_t r;
    asm("{ .reg .u64 t; cvta.to.shared.u64 t, %1; cvt.u32.u64 %0, t; }" : "=r"(r) : "l"(p));
    return r;
}
__device__ __forceinline__ void cp16(uint32_t d, const void* s) {
    asm volatile("cp.async.cg.shared.global [%0], [%1], 16;" :: "r"(d), "l"(s));
}
#define CP_COMMIT asm volatile("cp.async.commit_group;" ::: "memory")
#define CP_WAIT1  asm volatile("cp.async.wait_group 1;" ::: "memory")
#define CP_WAIT0  asm volatile("cp.async.wait_group 0;" ::: "memory")

__device__ __forceinline__ void ldsm4(uint32_t* r, uint32_t a) {
    asm volatile("ldmatrix.sync.aligned.m8n8.x4.shared.b16 {%0,%1,%2,%3}, [%4];"
        : "=r"(r[0]), "=r"(r[1]), "=r"(r[2]), "=r"(r[3]) : "r"(a));
}
#define MMA16816(D, A, B) asm volatile( \
    "mma.sync.aligned.m16n8k16.row.col.f32.f16.f16.f32 " \
    "{%0,%1,%2,%3}, {%4,%5,%6,%7}, {%8,%9}, {%0,%1,%2,%3};" \
    : "+f"((D)[0]), "+f"((D)[1]), "+f"((D)[2]), "+f"((D)[3]) \
    : "r"((A)[0]), "r"((A)[1]), "r"((A)[2]), "r"((A)[3]), "r"((B)[0]), "r"((B)[1]))

__device__ __forceinline__ uint32_t swz(uint32_t base, int row, int col) {
    uint32_t off = (uint32_t)(row * 128 + col);
    return base + (off ^ ((off >> 3) & 0x70));
}

// ---------------- prep kernels ----------------
__global__ void zero_pad_k() {
    int idx = blockIdx.x * blockDim.x + threadIdx.x;
    if (idx >= 65536) return;
    int b = idx >> 11, row = TT + ((idx >> 6) & 31), c = idx & 63;
    size_t off = ((size_t)b * TP + row) * 64 + c;
    g_xh[off] = __float2half(0.f);
    g_xl[off] = __float2half(0.f);
}

__global__ void __launch_bounds__(256) prep_x_k(const float* __restrict__ x) {
    __shared__ float xs[64][65];
    int b = blockIdx.y, t0 = blockIdx.x * 64, tid = threadIdx.x;
    for (int idx = tid; idx < 4096; idx += 256) {
        int c = idx >> 6, t = idx & 63;
        xs[c][t] = x[((size_t)b * 64 + c) * TT + t0 + t];
    }
    __syncthreads();
    for (int idx = tid; idx < 4096; idx += 256) {
        int t = idx >> 6, c = idx & 63;
        float v = xs[c][t];
        __half h = __float2half(v);
        __half l = __float2half(v - __half2float(h));
        size_t off = ((size_t)b * TP + t0 + t) * 64 + c;
        g_xh[off] = h;
        g_xl[off] = l;
    }
}

__global__ void prep_w_k(const float* __restrict__ w1, const float* __restrict__ w2) {
    int gid = blockIdx.x * blockDim.x + threadIdx.x;
    if (gid >= KW * 128 * 64) return;
    int k = gid >> 13, o = (gid >> 6) & 127, i = gid & 63;
    const float* w = (o >= 64) ? w2 : w1;
    g_wh[gid] = __float2half(w[((o & 63) * 64 + i) * KW + k]);
}

// ---------------- conv via mma.sync (HMMA fp16, x hi/lo 2-pass) ----------------
__global__ void __launch_bounds__(256) conv_k(const int* __restrict__ orig_len) {
    extern __shared__ __align__(16) char sm[];
    const int tid = threadIdx.x, wid = tid >> 5, lane = tid & 31;
    const int tb = blockIdx.x, b = blockIdx.y;
    const int t0 = tb * 128;
    const uint32_t smb = smem_u32(sm);
    const int wm = wid >> 1;      /* t-group 0..3 (32 rows)  */
    const int wn = wid & 1;       /* o-half 0..1 (64 cols)   */

    // ---- prologue: async-stage A window (148 rows) + B tap 0 ----
    {
        const uint4* sH = (const uint4*)g_xh + ((size_t)b * TP + t0) * 8;
        const uint4* sL = (const uint4*)g_xl + ((size_t)b * TP + t0) * 8;
        for (int idx = tid; idx < 1184; idx += 256) {
            uint32_t off = (uint32_t)((idx >> 3) * 128 + (idx & 7) * 16);
            uint32_t d = off ^ ((off >> 3) & 0x70);
            cp16(smb + OFF_AH + d, sH + idx);
            cp16(smb + OFF_AL + d, sL + idx);
        }
        const uint4* wH = (const uint4*)g_wh;
        for (int idx = tid; idx < 1024; idx += 256) {
            uint32_t off = (uint32_t)((idx >> 3) * 128 + (idx & 7) * 16);
            uint32_t d = off ^ ((off >> 3) & 0x70);
            cp16(smb + OFF_B + d, wH + idx);
        }
        CP_COMMIT;
    }

    float acc[2][8][4];
#pragma unroll
    for (int mt = 0; mt < 2; mt++)
#pragma unroll
        for (int nt = 0; nt < 8; nt++)
#pragma unroll
            for (int e = 0; e < 4; e++) acc[mt][nt][e] = 0.f;

#pragma unroll 1
    for (int k = 0; k < 21; k++) {
        const int buf = k & 1;
        if (k < 20) {   // stage next tap into other buffer
            const uint4* wH = (const uint4*)g_wh + (k + 1) * 1024;
            uint32_t db = smb + OFF_B + (buf ^ 1) * 16384;
            for (int idx = tid; idx < 1024; idx += 256) {
                uint32_t off = (uint32_t)((idx >> 3) * 128 + (idx & 7) * 16);
                uint32_t d = off ^ ((off >> 3) & 0x70);
                cp16(db + d, wH + idx);
            }
            CP_COMMIT;
            CP_WAIT1;
        } else {
            CP_WAIT0;
        }
        __syncthreads();

        const uint32_t bBaseH = smb + OFF_B + buf * 16384;
#pragma unroll
        for (int ks = 0; ks < 4; ks++) {
            const int colA = ks * 32 + ((lane >> 4) << 4);
            uint32_t ah[2][4], al[2][4], bh[8][2];
#pragma unroll
            for (int mt = 0; mt < 2; mt++) {
                int row = wm * 32 + k + mt * 16 + (lane & 15);
                ldsm4(ah[mt], swz(smb + OFF_AH, row, colA));
                ldsm4(al[mt], swz(smb + OFF_AL, row, colA));
            }
#pragma unroll
            for (int g = 0; g < 4; g++) {
                int row = wn * 64 + g * 16 + (lane & 15);
                uint32_t r[4];
                ldsm4(r, swz(bBaseH, row, colA));
                bh[2 * g][0] = r[0]; bh[2 * g][1] = r[2];
                bh[2 * g + 1][0] = r[1]; bh[2 * g + 1][1] = r[3];
            }
#pragma unroll
            for (int mt = 0; mt < 2; mt++)
#pragma unroll
                for (int nt = 0; nt < 8; nt++) MMA16816(acc[mt][nt], ah[mt], bh[nt]);
#pragma unroll
            for (int mt = 0; mt < 2; mt++)
#pragma unroll
                for (int nt = 0; nt < 8; nt++) MMA16816(acc[mt][nt], al[mt], bh[nt]);
        }
        __syncthreads();
    }

    // ---- epilogue: stage D[o][t] in smem (reuse A/B region) ----
    float* smD = (float*)sm;    // 128 x 132 floats = 67584 B
    {
        const int lo2 = 2 * (lane & 3), lt = lane >> 2;
#pragma unroll
        for (int mt = 0; mt < 2; mt++)
#pragma unroll
            for (int nt = 0; nt < 8; nt++) {
                int o = wn * 64 + nt * 8 + lo2;
                int t = wm * 32 + mt * 16 + lt;
                smD[o * 132 + t]           = acc[mt][nt][0];
                smD[(o + 1) * 132 + t]     = acc[mt][nt][1];
                smD[o * 132 + t + 8]       = acc[mt][nt][2];
                smD[(o + 1) * 132 + t + 8] = acc[mt][nt][3];
            }
    }
    __syncthreads();

    const int L = orig_len[b] - (KW - 1);
    const int strd = L >> 1, kern = L - strd;
    const int cta = b * 128 + tb;

#pragma unroll 1
    for (int oi = 0; oi < 16; oi++) {
        const int o = wid * 16 + oi;
        float4 v = *(const float4*)(smD + o * 132 + lane * 4);
        float vv[4] = {v.x, v.y, v.z, v.w};
        float s = 0.f, q = 0.f;
        float m0 = -FLT_MAX, m1 = -FLT_MAX, m2 = -FLT_MAX;
        const int tg0 = t0 + lane * 4;
#pragma unroll
        for (int e = 0; e < 4; e++) {
            int tg = tg0 + e;
            float xv = vv[e];
            if (tg < TCV) { s += xv; q += xv * xv; }
            if (o < 64) {
                if (tg < L) { m0 = fmaxf(m0, xv); if (tg >= strd) m2 = fmaxf(m2, xv); }
                if (tg < kern) m1 = fmaxf(m1, xv);
            }
        }
        if (o >= 64)   // conv2 raw output needed elementwise for avg-pool(leaky)
            *(float4*)(g_y2 + ((size_t)(b * 64 + (o - 64))) * TT + t0 + lane * 4) = v;
#pragma unroll
        for (int off = 16; off; off >>= 1) {
            s += __shfl_xor_sync(0xffffffffu, s, off);
            q += __shfl_xor_sync(0xffffffffu, q, off);
            m0 = fmaxf(m0, __shfl_xor_sync(0xffffffffu, m0, off));
            m1 = fmaxf(m1, __shfl_xor_sync(0xffffffffu, m1, off));
            m2 = fmaxf(m2, __shfl_xor_sync(0xffffffffu, m2, off));
        }
        if (lane == 0) {
            g_bs[o * 4096 + cta] = s;
            g_bs[(128 + o) * 4096 + cta] = q;
            if (o < 64) {
                float* p = g_part + ((b * 64 + o) * 3) * 128 + tb;
                p[0] = m0; p[128] = m1; p[256] = m2;
            }
        }
    }
}

// ---------------- BN stats reduce ----------------
__global__ void __launch_bounds__(256) stats_k() {
    __shared__ double sd[256];
    int slot = blockIdx.x, tid = threadIdx.x;
    double a = 0.0;
    for (int i = tid; i < 4096; i += 256) a += (double)g_bs[(size_t)slot * 4096 + i];
    sd[tid] = a;
    __syncthreads();
    for (int s = 128; s; s >>= 1) { if (tid < s) sd[tid] += sd[tid + s]; __syncthreads(); }
    if (tid == 0) {
        if (slot < 128) g_sumd[slot] = sd[0];
        else g_sqd[slot - 128] = sd[0];
    }
}

// ---------------- max-branch features (conv1) ----------------
__global__ void featmax_k(const float* __restrict__ g1, const float* __restrict__ b1) {
    int b = blockIdx.x, j = threadIdx.x;   // 192 threads
    if (j >= 192) return;
    int o, w;
    if (j < 64) { o = j; w = 0; } else { o = (j - 64) >> 1; w = 1 + ((j - 64) & 1); }
    const float* p = g_part + ((b * 64 + o) * 3 + w) * 128;
    float m = -FLT_MAX;
    for (int t = 0; t < 128; t++) m = fmaxf(m, p[t]);
    const double CNT = (double)BB * (double)TCV;
    double mu = g_sumd[o] / CNT;
    double va = g_sqd[o] / CNT - mu * mu;
    double scd = (double)g1[o] / sqrt(va + 1e-5);
    float z = (float)(scd * (double)m + ((double)b1[o] - mu * scd));
    z = (z > 0.f) ? z : 0.01f * z;
    g_feat[b * 384 + j] = z;
}

// ---------------- avg-branch (conv2): BN + leaky + windowed sums ----------------
__global__ void __launch_bounds__(256) pool2_k(const int* __restrict__ orig_len,
                                               const float* __restrict__ g2, const float* __restrict__ b2) {
    const int c = blockIdx.x, b = blockIdx.y;
    const int tid = threadIdx.x;
    const int L = orig_len[b] - (KW - 1);
    const int strd = L >> 1, kern = L - strd;

    const double CNT = (double)BB * (double)TCV;
    double mu = g_sumd[64 + c] / CNT;
    double va = g_sqd[64 + c] / CNT - mu * mu;
    double scd = (double)g2[c] / sqrt(va + 1e-5);
    const float sc = (float)scd;
    const float sh = (float)((double)b2[c] - mu * scd);

    const float* yr = g_y2 + ((size_t)b * 64 + c) * TT;
    float s0 = 0.f, s1 = 0.f, s2 = 0.f;
    for (int t = tid; t < L; t += 256) {
        float z = sc * yr[t] + sh;
        z = (z > 0.f) ? z : 0.01f * z;
        s0 += z;
        if (t < kern) s1 += z;
        if (t >= strd) s2 += z;
    }
#pragma unroll
    for (int off = 16; off; off >>= 1) {
        s0 += __shfl_down_sync(0xffffffffu, s0, off);
        s1 += __shfl_down_sync(0xffffffffu, s1, off);
        s2 += __shfl_down_sync(0xffffffffu, s2, off);
    }
    __shared__ float red[8][3];
    if ((tid & 31) == 0) { int w = tid >> 5; red[w][0] = s0; red[w][1] = s1; red[w][2] = s2; }
    __syncthreads();
    if (tid == 0) {
        float t0v = 0.f, t1v = 0.f, t2v = 0.f;
#pragma unroll
        for (int w = 0; w < 8; w++) { t0v += red[w][0]; t1v += red[w][1]; t2v += red[w][2]; }
        float* f = g_feat + b * 384;
        f[192 + c] = t0v / (float)L;
        f[256 + 2 * c]     = t1v / (float)kern;
        f[256 + 2 * c + 1] = t2v / (float)kern;
    }
}

// ---------------- FC head ----------------
__global__ void fc_k(const float* __restrict__ fc_w, const float* __restrict__ fc_b,
                     float* __restrict__ out) {
    int tid = threadIdx.x;
    if (tid >= BB * 2) return;
    int b = tid >> 1, task = tid & 1;
    const float* f = g_feat + b * 384;
    const float* w = fc_w + task * 384;
    float acc = fc_b[task];
#pragma unroll 8
    for (int j = 0; j < 384; j++) acc += f[j] * w[j];
    out[b * 2 + task] = acc;
}

// ---------------- launch ----------------
extern "C" void kernel_launch(void* const* d_in, const int* in_sizes, int n_in,
                              void* d_out, int out_size) {
    const float* x        = (const float*)d_in[0];
    const int*   orig_len = (const int*)d_in[1];
    const float* w1   = (const float*)d_in[2];
    const float* g1   = (const float*)d_in[3];
    const float* b1   = (const float*)d_in[4];
    const float* w2   = (const float*)d_in[5];
    const float* g2   = (const float*)d_in[6];
    const float* b2   = (const float*)d_in[7];
    const float* fc_w = (const float*)d_in[8];
    const float* fc_b = (const float*)d_in[9];
    float* out = (float*)d_out;

    cudaFuncSetAttribute(conv_k, cudaFuncAttributeMaxDynamicSharedMemorySize, SMEM_TOTAL);

    zero_pad_k<<<256, 256>>>();
    dim3 xg(256, BB);
    prep_x_k<<<xg, 256>>>(x);
    prep_w_k<<<(KW * 128 * 64 + 255) / 256, 256>>>(w1, w2);

    dim3 cg(128, BB);
    conv_k<<<cg, 256, SMEM_TOTAL>>>(orig_len);

    stats_k<<<256, 256>>>();
    featmax_k<<<BB, 192>>>(g1, b1);
    dim3 pg(64, BB);
    pool2_k<<<pg, 256>>>(orig_len, g2, b2);

    fc_k<<<1, 64>>>(fc_w, fc_b, out);
}